// round 13
// baseline (speedup 1.0000x reference)
#include <cuda_runtime.h>
#include <cuda_fp16.h>
#include <cstdint>
#include <math.h>

#define D        10
#define NUMF     16
#define DIN      36
#define H        128
#define CS1      1
#define CS2      3
#define TILE_M   128
#define THREADS  128

#define E1_TOK (TILE_M + 2*CS1)   // 130
#define E2_TOK (TILE_M + 2*CS2)   // 134
#define PW     136                 // smem plane stride: 136 % 32 == 8 -> conflict-free frags
#define XPLANES 18                 // planes 0..17 stored in g_X (bias planes are constant)
#define XWORDS  (XPLANES * TILE_M) // 2304 words per tile
#define XCHUNKS (XWORDS / 4)       // 576 16B chunks per tile
#define BUFWORDS (20 * PW)         // smem buffer: 20 planes
#define VOCAB_MAX 65536
#define MAX_TILES 7936

// fp16 tables: row = 16 halves (10 used) = 32B
__device__ uint4 g_T1h[VOCAB_MAX * 2];
__device__ uint4 g_T2h[VOCAB_MAX * 2];
// x planes: [tile][plane 0..17][128 rows], half2 words
__device__ uint32_t g_X[(size_t)MAX_TILES * XWORDS];

__device__ __forceinline__ uint32_t h2pair(float a, float b) {
    __half2 h = __floats2half2_rn(a, b);
    return *reinterpret_cast<uint32_t*>(&h);
}
__device__ __forceinline__ uint32_t smem_u32(const void* p) {
    return (uint32_t)__cvta_generic_to_shared(p);
}
__device__ __forceinline__ void cp_async16(uint32_t dst, const void* src) {
    asm volatile("cp.async.cg.shared.global [%0], [%1], 16;" :: "r"(dst), "l"(src) : "memory");
}
#define CP_COMMIT() asm volatile("cp.async.commit_group;" ::: "memory")
#define CP_WAIT0()  asm volatile("cp.async.wait_group 0;" ::: "memory")

__global__ void convert_tables_kernel(const float* __restrict__ T1,
                                      const float* __restrict__ T2, int vocab) {
    int idx = blockIdx.x * blockDim.x + threadIdx.x;
    int total = vocab * 2;
    for (int e = idx; e < total; e += gridDim.x * blockDim.x) {
        int r = e >> 1, hf = e & 1;
        const float* r1 = T1 + r * D;
        const float* r2 = T2 + r * D;
        uint4 v1, v2;
        if (hf == 0) {
            v1.x = h2pair(r1[0], r1[1]); v1.y = h2pair(r1[2], r1[3]);
            v1.z = h2pair(r1[4], r1[5]); v1.w = h2pair(r1[6], r1[7]);
            v2.x = h2pair(r2[0], r2[1]); v2.y = h2pair(r2[2], r2[3]);
            v2.z = h2pair(r2[4], r2[5]); v2.w = h2pair(r2[6], r2[7]);
        } else {
            v1.x = h2pair(r1[8], r1[9]); v1.y = 0u; v1.z = 0u; v1.w = 0u;
            v2.x = h2pair(r2[8], r2[9]); v2.y = 0u; v2.z = 0u; v2.w = 0u;
        }
        g_T1h[e] = v1;
        g_T2h[e] = v2;
    }
}

__device__ __forceinline__ void load_rowh(const uint4* __restrict__ tab, int tok,
                                          uint32_t o[5]) {
    if (tok >= 0) {
        uint4 a = __ldg(tab + tok * 2);
        uint32_t b = __ldg(reinterpret_cast<const uint32_t*>(tab + tok * 2 + 1));
        o[0] = a.x; o[1] = a.y; o[2] = a.z; o[3] = a.w; o[4] = b;
    } else {
        o[0] = 0u; o[1] = 0u; o[2] = 0u; o[3] = 0u; o[4] = 0u;
    }
}

// ===================== Kernel 1: build x planes =====================
__global__ __launch_bounds__(THREADS)
void build_x_kernel(const int* __restrict__ t1, const int* __restrict__ t2,
                    const float* __restrict__ numf, int n, int nTiles)
{
    __shared__ uint32_t s_e1[E1_TOK * 5];
    __shared__ uint32_t s_e2[E2_TOK * 5];
    __shared__ int s_tk1[E1_TOK];
    __shared__ int s_tk2[E2_TOK];
    __shared__ uint32_t s_nh[TILE_M * 8];

    const int tid  = threadIdx.x;
    const int tile = blockIdx.x;
    const int r0g  = tile * TILE_M;
    const int i    = r0g + tid;
    const float4* numf4 = reinterpret_cast<const float4*>(numf);
    const long nF4 = (long)n * 4;

    // tokens
    for (int r = tid; r < E1_TOK; r += THREADS) {
        int g = r0g - CS1 + r;
        s_tk1[r] = (g >= 0 && g < n) ? t1[g] : -1;
    }
    for (int r = tid; r < E2_TOK; r += THREADS) {
        int g = r0g - CS2 + r;
        s_tk2[r] = (g >= 0 && g < n) ? t2[g] : -1;
    }
    __syncthreads();

    // gather + numeric stage
    for (int r = tid; r < E1_TOK; r += THREADS) {
        uint32_t o[5];
        load_rowh(g_T1h, s_tk1[r], o);
        #pragma unroll
        for (int q = 0; q < 5; q++) s_e1[r * 5 + q] = o[q];
    }
    for (int r = tid; r < E2_TOK; r += THREADS) {
        uint32_t o[5];
        load_rowh(g_T2h, s_tk2[r], o);
        #pragma unroll
        for (int q = 0; q < 5; q++) s_e2[r * 5 + q] = o[q];
    }
    #pragma unroll
    for (int u = 0; u < 4; u++) {
        int e = u * THREADS + tid;
        long gf4 = (long)tile * (TILE_M * 4) + e;
        float4 v = (gf4 < nF4) ? __ldg(numf4 + gf4) : make_float4(0.f, 0.f, 0.f, 0.f);
        s_nh[2*e]     = h2pair(v.x, v.y);
        s_nh[2*e + 1] = h2pair(v.z, v.w);
    }
    __syncthreads();

    // x-build -> global planes
    uint32_t* gxt = g_X + (size_t)tile * XWORDS;
    const __half2* e1h = reinterpret_cast<const __half2*>(s_e1);
    const __half2* e2h = reinterpret_cast<const __half2*>(s_e2);

    int lo1 = max(i - CS1, 0), hi1 = min(i + CS1 + 1, n);
    int lo2 = max(i - CS2, 0), hi2 = min(i + CS2 + 1, n);
    __half2 inv1 = __float2half2_rn(__fdividef(1.0f, (float)max(hi1 - lo1, 1)));
    __half2 inv2 = __float2half2_rn(__fdividef(1.0f, (float)max(hi2 - lo2, 1)));

    #pragma unroll
    for (int q = 0; q < 5; q++) {
        __half2 a = e1h[(tid + 0) * 5 + q];
        __half2 b = e1h[(tid + 1) * 5 + q];
        __half2 c = e1h[(tid + 2) * 5 + q];
        __half2 r = __hmul2(__hadd2(__hadd2(a, b), c), inv1);
        gxt[q * TILE_M + tid] = *reinterpret_cast<uint32_t*>(&r);
    }
    #pragma unroll
    for (int q = 0; q < 5; q++) {
        __half2 v0 = e2h[(tid + 0) * 5 + q];
        __half2 v1 = e2h[(tid + 1) * 5 + q];
        __half2 v2 = e2h[(tid + 2) * 5 + q];
        __half2 v3 = e2h[(tid + 3) * 5 + q];
        __half2 v4 = e2h[(tid + 4) * 5 + q];
        __half2 v5 = e2h[(tid + 5) * 5 + q];
        __half2 v6 = e2h[(tid + 6) * 5 + q];
        __half2 s = __hadd2(__hadd2(__hadd2(v0, v1), __hadd2(v2, v3)),
                            __hadd2(__hadd2(v4, v5), v6));
        __half2 r = __hmul2(s, inv2);
        gxt[(5 + q) * TILE_M + tid] = *reinterpret_cast<uint32_t*>(&r);
    }
    #pragma unroll
    for (int j = 0; j < 8; j++)
        gxt[(10 + j) * TILE_M + tid] = s_nh[tid * 8 + j];
}

// ===================== Kernel 2: persistent GEMM =====================
__device__ __forceinline__ void mma16(float d[4],
                                      uint32_t a0, uint32_t a1, uint32_t a2, uint32_t a3,
                                      uint32_t b0, uint32_t b1) {
    asm volatile(
        "mma.sync.aligned.m16n8k16.row.col.f32.f16.f16.f32 "
        "{%0,%1,%2,%3}, {%4,%5,%6,%7}, {%8,%9}, {%0,%1,%2,%3};"
        : "+f"(d[0]), "+f"(d[1]), "+f"(d[2]), "+f"(d[3])
        : "r"(a0), "r"(a1), "r"(a2), "r"(a3), "r"(b0), "r"(b1));
}
__device__ __forceinline__ void mma8(float d[4], uint32_t a0, uint32_t a1, uint32_t b0) {
    asm volatile(
        "mma.sync.aligned.m16n8k8.row.col.f32.f16.f16.f32 "
        "{%0,%1,%2,%3}, {%4,%5}, {%6}, {%0,%1,%2,%3};"
        : "+f"(d[0]), "+f"(d[1]), "+f"(d[2]), "+f"(d[3])
        : "r"(a0), "r"(a1), "r"(b0));
}

__global__ __launch_bounds__(THREADS, 7)
void gemm_kernel(const float* __restrict__ W1, const float* __restrict__ b1,
                 const float* __restrict__ W2, const float* __restrict__ b2,
                 float* __restrict__ out, int n, int nTiles)
{
    __shared__ uint32_t s_A[2 * BUFWORDS];
    __shared__ float s_part[4][TILE_M];

    const int tid  = threadIdx.x;
    const int wid  = tid >> 5;
    const int lane = tid & 31;

    // B fragments (fp16), bias folded at k==36
    uint32_t B[4][5];
    float w2r[4][2];
    {
        const int nsub = lane >> 2;
        const int ksub = (lane & 3) * 2;
        #pragma unroll
        for (int j = 0; j < 4; j++) {
            int nn = wid * 32 + j * 8 + nsub;
            #pragma unroll
            for (int p = 0; p < 5; p++) {
                int k0 = p * 8 + ksub;
                float wv0 = (k0     < DIN) ? W1[k0 * H + nn]     : ((k0     == DIN) ? b1[nn] : 0.0f);
                float wv1 = (k0 + 1 < DIN) ? W1[(k0 + 1)*H + nn] : ((k0 + 1 == DIN) ? b1[nn] : 0.0f);
                B[j][p] = h2pair(wv0, wv1);
            }
            int nc = wid * 32 + j * 8 + (lane & 3) * 2;
            w2r[j][0] = W2[nc];
            w2r[j][1] = W2[nc + 1];
        }
    }
    const float b2v = b2[0];
    const int ar = lane >> 2;
    const int kb = lane & 3;
    const uint32_t sA0 = smem_u32(s_A);

    // bias planes (18,19) constant in both buffers
    s_A[0 * BUFWORDS + 18 * PW + tid] = 0x00003C00u;
    s_A[0 * BUFWORDS + 19 * PW + tid] = 0u;
    s_A[1 * BUFWORDS + 18 * PW + tid] = 0x00003C00u;
    s_A[1 * BUFWORDS + 19 * PW + tid] = 0u;

    // prologue: fill buffer 0 with tile0
    const int tile0 = blockIdx.x;
    {
        const uint32_t* src = g_X + (size_t)tile0 * XWORDS;
        #pragma unroll
        for (int u = 0; u < 5; u++) {
            int c = tid + u * THREADS;
            if (c < XCHUNKS) {
                int kw = c >> 5, rr = (c & 31) * 4;
                cp_async16(sA0 + (kw * PW + rr) * 4, src + c * 4);
            }
        }
        CP_COMMIT();
        CP_WAIT0();
    }
    __syncthreads();

    int b = 0;
    for (int tile = tile0; tile < nTiles; tile += gridDim.x) {
        // issue cp.async for tile t+1 into other buffer
        const int nt = tile + gridDim.x;
        if (nt < nTiles) {
            const uint32_t* src = g_X + (size_t)nt * XWORDS;
            const uint32_t dstB = sA0 + (b ^ 1) * BUFWORDS * 4;
            #pragma unroll
            for (int u = 0; u < 5; u++) {
                int c = tid + u * THREADS;
                if (c < XCHUNKS) {
                    int kw = c >> 5, rr = (c & 31) * 4;
                    cp_async16(dstB + (kw * PW + rr) * 4, src + c * 4);
                }
            }
        }
        CP_COMMIT();

        const uint32_t* Ab = s_A + b * BUFWORDS;

        // MMA over 8 m-tiles
        #pragma unroll
        for (int mt = 0; mt < 8; mt++) {
            float Dacc[4][4];
            #pragma unroll
            for (int j = 0; j < 4; j++) {
                Dacc[j][0] = 0.f; Dacc[j][1] = 0.f; Dacc[j][2] = 0.f; Dacc[j][3] = 0.f;
            }
            const int rb = mt * 16;
            const int ra = rb + ar;

            #pragma unroll
            for (int s = 0; s < 2; s++) {
                const int kw = s * 8 + kb;
                uint32_t a0 = Ab[kw * PW + ra];
                uint32_t a1 = Ab[kw * PW + ra + 8];
                uint32_t a2 = Ab[(kw + 4) * PW + ra];
                uint32_t a3 = Ab[(kw + 4) * PW + ra + 8];
                #pragma unroll
                for (int j = 0; j < 4; j++)
                    mma16(Dacc[j], a0, a1, a2, a3, B[j][2*s], B[j][2*s + 1]);
            }
            {
                const int kw = 16 + kb;
                uint32_t a0 = Ab[kw * PW + ra];
                uint32_t a1 = Ab[kw * PW + ra + 8];
                #pragma unroll
                for (int j = 0; j < 4; j++) mma8(Dacc[j], a0, a1, B[j][4]);
            }

            float p0 = 0.0f, p1 = 0.0f;
            #pragma unroll
            for (int j = 0; j < 4; j++) {
                p0 = fmaf(fmaxf(Dacc[j][0], 0.f), w2r[j][0], p0);
                p0 = fmaf(fmaxf(Dacc[j][1], 0.f), w2r[j][1], p0);
                p1 = fmaf(fmaxf(Dacc[j][2], 0.f), w2r[j][0], p1);
                p1 = fmaf(fmaxf(Dacc[j][3], 0.f), w2r[j][1], p1);
            }
            p0 += __shfl_xor_sync(0xFFFFFFFF, p0, 1);
            p0 += __shfl_xor_sync(0xFFFFFFFF, p0, 2);
            p1 += __shfl_xor_sync(0xFFFFFFFF, p1, 1);
            p1 += __shfl_xor_sync(0xFFFFFFFF, p1, 2);
            if ((lane & 3) == 0) {
                s_part[wid][rb + ar]     = p0;
                s_part[wid][rb + ar + 8] = p1;
            }
        }

        CP_WAIT0();          // next buffer landed
        __syncthreads();     // s_part + next buffer visible

        const int i = tile * TILE_M + tid;
        if (i < n) {
            float s = s_part[0][tid] + s_part[1][tid] + s_part[2][tid] + s_part[3][tid] + b2v;
            out[i] = __fdividef(1.0f, 1.0f + __expf(-s));
        }
        __syncthreads();     // out reads done before next epilogue writes s_part
        b ^= 1;
    }
}

extern "C" void kernel_launch(void* const* d_in, const int* in_sizes, int n_in,
                              void* d_out, int out_size) {
    const int*   t1   = (const int*)d_in[0];
    const int*   t2   = (const int*)d_in[1];
    const float* numf = (const float*)d_in[2];
    const float* T1   = (const float*)d_in[3];
    const float* T2   = (const float*)d_in[4];
    const float* W1   = (const float*)d_in[5];
    const float* b1   = (const float*)d_in[6];
    const float* W2   = (const float*)d_in[7];
    const float* b2   = (const float*)d_in[8];
    float* out = (float*)d_out;

    int n = in_sizes[0];
    int vocab = in_sizes[3] / D;
    if (vocab > VOCAB_MAX) vocab = VOCAB_MAX;
    int nTiles = (n + TILE_M - 1) / TILE_M;
    if (nTiles > MAX_TILES) nTiles = MAX_TILES;

    int cblocks = (vocab * 2 + 255) / 256;
    convert_tables_kernel<<<cblocks, 256>>>(T1, T2, vocab);

    build_x_kernel<<<nTiles, THREADS>>>(t1, t2, numf, n, nTiles);

    int grid = 148 * 7;
    if (grid > nTiles) grid = nTiles;
    gemm_kernel<<<grid, THREADS>>>(W1, b1, W2, b2, out, n, nTiles);
}

// round 14
// speedup vs baseline: 1.6014x; 1.6014x over previous
#include <cuda_runtime.h>
#include <cuda_fp16.h>
#include <cstdint>
#include <math.h>

#define D        10
#define NUMF     16
#define DIN      36
#define H        128
#define CS1      1
#define CS2      3
#define TILE_M   256
#define THREADS  256
#define NW       8

#define E1_TOK (TILE_M + 2*CS1)   // 258
#define E2_TOK (TILE_M + 2*CS2)   // 262
#define TOT_ROWS (E1_TOK + E2_TOK) // 520 (rows <258 -> e1, else e2)
#define PW     264                 // plane stride words: 264 % 32 == 8 -> conflict-free frags
#define VOCAB_MAX 65536

// fp16 tables: row = 16 halves (10 used) = 32B
__device__ uint4 g_T1h[VOCAB_MAX * 2];
__device__ uint4 g_T2h[VOCAB_MAX * 2];

__device__ __forceinline__ uint32_t h2pair(float a, float b) {
    __half2 h = __floats2half2_rn(a, b);
    return *reinterpret_cast<uint32_t*>(&h);
}

__global__ void convert_tables_kernel(const float* __restrict__ T1,
                                      const float* __restrict__ T2, int vocab) {
    int idx = blockIdx.x * blockDim.x + threadIdx.x;
    int total = vocab * 2;
    for (int e = idx; e < total; e += gridDim.x * blockDim.x) {
        int r = e >> 1, hf = e & 1;
        const float* r1 = T1 + r * D;
        const float* r2 = T2 + r * D;
        uint4 v1, v2;
        if (hf == 0) {
            v1.x = h2pair(r1[0], r1[1]); v1.y = h2pair(r1[2], r1[3]);
            v1.z = h2pair(r1[4], r1[5]); v1.w = h2pair(r1[6], r1[7]);
            v2.x = h2pair(r2[0], r2[1]); v2.y = h2pair(r2[2], r2[3]);
            v2.z = h2pair(r2[4], r2[5]); v2.w = h2pair(r2[6], r2[7]);
        } else {
            v1.x = h2pair(r1[8], r1[9]); v1.y = 0u; v1.z = 0u; v1.w = 0u;
            v2.x = h2pair(r2[8], r2[9]); v2.y = 0u; v2.z = 0u; v2.w = 0u;
        }
        g_T1h[e] = v1;
        g_T2h[e] = v2;
    }
}

__device__ __forceinline__ void load_rowh(const uint4* __restrict__ tab, int tok,
                                          uint32_t o[5]) {
    if (tok >= 0) {
        uint4 a = __ldg(tab + tok * 2);
        uint32_t b = __ldg(reinterpret_cast<const uint32_t*>(tab + tok * 2 + 1));
        o[0] = a.x; o[1] = a.y; o[2] = a.z; o[3] = a.w; o[4] = b;
    } else {
        o[0] = 0u; o[1] = 0u; o[2] = 0u; o[3] = 0u; o[4] = 0u;
    }
}

__device__ __forceinline__ void mma16(float d[4],
                                      uint32_t a0, uint32_t a1, uint32_t a2, uint32_t a3,
                                      uint32_t b0, uint32_t b1) {
    asm volatile(
        "mma.sync.aligned.m16n8k16.row.col.f32.f16.f16.f32 "
        "{%0,%1,%2,%3}, {%4,%5,%6,%7}, {%8,%9}, {%0,%1,%2,%3};"
        : "+f"(d[0]), "+f"(d[1]), "+f"(d[2]), "+f"(d[3])
        : "r"(a0), "r"(a1), "r"(a2), "r"(a3), "r"(b0), "r"(b1));
}
__device__ __forceinline__ void mma8(float d[4], uint32_t a0, uint32_t a1, uint32_t b0) {
    asm volatile(
        "mma.sync.aligned.m16n8k8.row.col.f32.f16.f16.f32 "
        "{%0,%1,%2,%3}, {%4,%5}, {%6}, {%0,%1,%2,%3};"
        : "+f"(d[0]), "+f"(d[1]), "+f"(d[2]), "+f"(d[3])
        : "r"(a0), "r"(a1), "r"(b0));
}

__global__ __launch_bounds__(THREADS, 4)
void wordemb_w8_kernel(
    const int*   __restrict__ t1,
    const int*   __restrict__ t2,
    const float* __restrict__ numf,
    const float* __restrict__ W1,
    const float* __restrict__ b1,
    const float* __restrict__ W2,
    const float* __restrict__ b2,
    float* __restrict__ out,
    int n, int nTiles)
{
    __shared__ uint32_t s_A[20 * PW];       // 21120 B
    __shared__ uint32_t s_e1[E1_TOK * 5];   // 5160 B
    __shared__ uint32_t s_e2[E2_TOK * 5];   // 5240 B
    __shared__ int   s_tk[2][TOT_ROWS];     // 4160 B (unified e1|e2)
    __shared__ float s_part[NW][TILE_M];    // 8192 B

    const int tid  = threadIdx.x;
    const int wid  = tid >> 5;
    const int lane = tid & 31;
    const float4* numf4 = reinterpret_cast<const float4*>(numf);
    const long nF4 = (long)n * 4;

    // ---- B fragments: warp owns 16 columns (2 j-tiles); bias folded at k==36 ----
    uint32_t B[2][5];
    float w2r[2][2];
    {
        const int nsub = lane >> 2;
        const int ksub = (lane & 3) * 2;
        #pragma unroll
        for (int j = 0; j < 2; j++) {
            int nn = wid * 16 + j * 8 + nsub;
            #pragma unroll
            for (int p = 0; p < 5; p++) {
                int k0 = p * 8 + ksub;
                float wv0 = (k0     < DIN) ? W1[k0 * H + nn]     : ((k0     == DIN) ? b1[nn] : 0.0f);
                float wv1 = (k0 + 1 < DIN) ? W1[(k0 + 1)*H + nn] : ((k0 + 1 == DIN) ? b1[nn] : 0.0f);
                B[j][p] = h2pair(wv0, wv1);
            }
            int nc = wid * 16 + j * 8 + (lane & 3) * 2;
            w2r[j][0] = W2[nc];
            w2r[j][1] = W2[nc + 1];
        }
    }
    const float b2v = b2[0];
    const int ar = lane >> 2;
    const int kb = lane & 3;

    const __half2* e1h = reinterpret_cast<const __half2*>(s_e1);
    const __half2* e2h = reinterpret_cast<const __half2*>(s_e2);
    __half2* Ahh = reinterpret_cast<__half2*>(s_A);

    // ===== Prologue: tokens(t0); gather(t0); tokens(t1); numeric(t0); bias =====
    const int tile0 = blockIdx.x;
    {
        int r0g = tile0 * TILE_M;
        for (int er = tid; er < TOT_ROWS; er += THREADS) {
            int g = (er < E1_TOK) ? (r0g - CS1 + er) : (r0g - CS2 + (er - E1_TOK));
            int tok = -1;
            if (g >= 0 && g < n) tok = (er < E1_TOK) ? t1[g] : t2[g];
            s_tk[0][er] = tok;
        }
    }
    __syncthreads();
    for (int er = tid; er < TOT_ROWS; er += THREADS) {
        uint32_t o[5];
        const uint4* tab = (er < E1_TOK) ? g_T1h : g_T2h;
        load_rowh(tab, s_tk[0][er], o);
        uint32_t* dst = (er < E1_TOK) ? &s_e1[er * 5] : &s_e2[(er - E1_TOK) * 5];
        #pragma unroll
        for (int q = 0; q < 5; q++) dst[q] = o[q];
    }
    {
        int nt = tile0 + gridDim.x;
        if (nt < nTiles) {
            int r0g = nt * TILE_M;
            for (int er = tid; er < TOT_ROWS; er += THREADS) {
                int g = (er < E1_TOK) ? (r0g - CS1 + er) : (r0g - CS2 + (er - E1_TOK));
                int tok = -1;
                if (g >= 0 && g < n) tok = (er < E1_TOK) ? t1[g] : t2[g];
                s_tk[1][er] = tok;
            }
        }
    }
    #pragma unroll
    for (int u = 0; u < 4; u++) {
        int e = u * THREADS + tid;
        long gf4 = (long)tile0 * (TILE_M * 4) + e;
        float4 v = (gf4 < nF4) ? __ldg(numf4 + gf4) : make_float4(0.f, 0.f, 0.f, 0.f);
        int r = e >> 2, q = e & 3;
        s_A[(10 + 2*q) * PW + r] = h2pair(v.x, v.y);
        s_A[(11 + 2*q) * PW + r] = h2pair(v.z, v.w);
    }
    s_A[18 * PW + tid] = 0x00003C00u;   // (fp16 1.0, 0.0) bias channel k=36
    s_A[19 * PW + tid] = 0u;
    __syncthreads();

    int p = 0;   // s_tk[p^1] holds tokens(t+1)
    for (int tile = tile0; tile < nTiles; tile += gridDim.x) {
        const int i = tile * TILE_M + tid;

        // ===== Phase A: half2 x-build -> e-planes 0..9 =====
        {
            int lo1 = max(i - CS1, 0), hi1 = min(i + CS1 + 1, n);
            int lo2 = max(i - CS2, 0), hi2 = min(i + CS2 + 1, n);
            __half2 inv1 = __float2half2_rn(__fdividef(1.0f, (float)max(hi1 - lo1, 1)));
            __half2 inv2 = __float2half2_rn(__fdividef(1.0f, (float)max(hi2 - lo2, 1)));

            #pragma unroll
            for (int q = 0; q < 5; q++) {
                __half2 a = e1h[(tid + 0) * 5 + q];
                __half2 b = e1h[(tid + 1) * 5 + q];
                __half2 c = e1h[(tid + 2) * 5 + q];
                Ahh[q * PW + tid] = __hmul2(__hadd2(__hadd2(a, b), c), inv1);
            }
            #pragma unroll
            for (int q = 0; q < 5; q++) {
                __half2 v0 = e2h[(tid + 0) * 5 + q];
                __half2 v1 = e2h[(tid + 1) * 5 + q];
                __half2 v2 = e2h[(tid + 2) * 5 + q];
                __half2 v3 = e2h[(tid + 3) * 5 + q];
                __half2 v4 = e2h[(tid + 4) * 5 + q];
                __half2 v5 = e2h[(tid + 5) * 5 + q];
                __half2 v6 = e2h[(tid + 6) * 5 + q];
                __half2 s = __hadd2(__hadd2(__hadd2(v0, v1), __hadd2(v2, v3)),
                                    __hadd2(__hadd2(v4, v5), v6));
                Ahh[(5 + q) * PW + tid] = __hmul2(s, inv2);
            }
        }
        __syncthreads();

        // ===== Phase B: prefetch(t+1) + MMA =====
        const int nt1 = tile + gridDim.x;
        const int nt2 = nt1 + gridDim.x;
        const bool hasN1 = nt1 < nTiles;
        const bool hasN2 = nt2 < nTiles;

        // gather prefetch: 3 row-slots (er = tid, 256+tid, 512+tid<8)
        uint32_t pg[3][5];
        if (hasN1) {
            #pragma unroll
            for (int u = 0; u < 3; u++) {
                int er = u * THREADS + tid;
                if (er < TOT_ROWS) {
                    const uint4* tab = (er < E1_TOK) ? g_T1h : g_T2h;
                    load_rowh(tab, s_tk[p ^ 1][er], pg[u]);
                }
            }
        }
        // numeric(t+1) coalesced
        uint32_t nvh[8];
        if (hasN1) {
            #pragma unroll
            for (int u = 0; u < 4; u++) {
                int e = u * THREADS + tid;
                long gf4 = (long)nt1 * (TILE_M * 4) + e;
                float4 v = (gf4 < nF4) ? __ldg(numf4 + gf4) : make_float4(0.f, 0.f, 0.f, 0.f);
                nvh[2*u]     = h2pair(v.x, v.y);
                nvh[2*u + 1] = h2pair(v.z, v.w);
            }
        }
        // tokens(t+2)
        int ptk[3];
        if (hasN2) {
            int nr0 = nt2 * TILE_M;
            #pragma unroll
            for (int u = 0; u < 3; u++) {
                int er = u * THREADS + tid;
                int tok = -1;
                if (er < TOT_ROWS) {
                    int g = (er < E1_TOK) ? (nr0 - CS1 + er) : (nr0 - CS2 + (er - E1_TOK));
                    if (g >= 0 && g < n) tok = (er < E1_TOK) ? t1[g] : t2[g];
                }
                ptk[u] = tok;
            }
        }

        // ---- MMA over 16 m-tiles (fp16 single product, 2 j-tiles/warp) ----
        #pragma unroll
        for (int mt = 0; mt < 16; mt++) {
            float Dacc[2][4];
            #pragma unroll
            for (int j = 0; j < 2; j++) {
                Dacc[j][0] = 0.f; Dacc[j][1] = 0.f; Dacc[j][2] = 0.f; Dacc[j][3] = 0.f;
            }
            const int rb = mt * 16;
            const int ra = rb + ar;

            #pragma unroll
            for (int s = 0; s < 2; s++) {
                const int kw = s * 8 + kb;
                uint32_t a0 = s_A[kw * PW + ra];
                uint32_t a1 = s_A[kw * PW + ra + 8];
                uint32_t a2 = s_A[(kw + 4) * PW + ra];
                uint32_t a3 = s_A[(kw + 4) * PW + ra + 8];
                #pragma unroll
                for (int j = 0; j < 2; j++)
                    mma16(Dacc[j], a0, a1, a2, a3, B[j][2*s], B[j][2*s + 1]);
            }
            {
                const int kw = 16 + kb;
                uint32_t a0 = s_A[kw * PW + ra];
                uint32_t a1 = s_A[kw * PW + ra + 8];
                #pragma unroll
                for (int j = 0; j < 2; j++) mma8(Dacc[j], a0, a1, B[j][4]);
            }

            float p0 = 0.0f, p1 = 0.0f;
            #pragma unroll
            for (int j = 0; j < 2; j++) {
                p0 = fmaf(fmaxf(Dacc[j][0], 0.f), w2r[j][0], p0);
                p0 = fmaf(fmaxf(Dacc[j][1], 0.f), w2r[j][1], p0);
                p1 = fmaf(fmaxf(Dacc[j][2], 0.f), w2r[j][0], p1);
                p1 = fmaf(fmaxf(Dacc[j][3], 0.f), w2r[j][1], p1);
            }
            p0 += __shfl_xor_sync(0xFFFFFFFF, p0, 1);
            p0 += __shfl_xor_sync(0xFFFFFFFF, p0, 2);
            p1 += __shfl_xor_sync(0xFFFFFFFF, p1, 1);
            p1 += __shfl_xor_sync(0xFFFFFFFF, p1, 2);
            if ((lane & 3) == 0) {
                s_part[wid][rb + ar]     = p0;
                s_part[wid][rb + ar + 8] = p1;
            }
        }

        // ---- write prefetched e-rows (s_e not read during MMA) ----
        if (hasN1) {
            #pragma unroll
            for (int u = 0; u < 3; u++) {
                int er = u * THREADS + tid;
                if (er < TOT_ROWS) {
                    uint32_t* dst = (er < E1_TOK) ? &s_e1[er * 5] : &s_e2[(er - E1_TOK) * 5];
                    #pragma unroll
                    for (int q = 0; q < 5; q++) dst[q] = pg[u][q];
                }
            }
        }
        __syncthreads();

        // ===== Phase C: out + numeric planes(t+1) + token stash(t+2) =====
        if (i < n) {
            float s = b2v;
            #pragma unroll
            for (int w = 0; w < NW; w++) s += s_part[w][tid];
            out[i] = __fdividef(1.0f, 1.0f + __expf(-s));
        }
        if (hasN1) {
            #pragma unroll
            for (int u = 0; u < 4; u++) {
                int e = u * THREADS + tid;
                int r = e >> 2, q = e & 3;
                s_A[(10 + 2*q) * PW + r] = nvh[2*u];
                s_A[(11 + 2*q) * PW + r] = nvh[2*u + 1];
            }
        }
        if (hasN2) {
            #pragma unroll
            for (int u = 0; u < 3; u++) {
                int er = u * THREADS + tid;
                if (er < TOT_ROWS) s_tk[p][er] = ptk[u];
            }
        }
        __syncthreads();
        p ^= 1;
    }
}

extern "C" void kernel_launch(void* const* d_in, const int* in_sizes, int n_in,
                              void* d_out, int out_size) {
    const int*   t1   = (const int*)d_in[0];
    const int*   t2   = (const int*)d_in[1];
    const float* numf = (const float*)d_in[2];
    const float* T1   = (const float*)d_in[3];
    const float* T2   = (const float*)d_in[4];
    const float* W1   = (const float*)d_in[5];
    const float* b1   = (const float*)d_in[6];
    const float* W2   = (const float*)d_in[7];
    const float* b2   = (const float*)d_in[8];
    float* out = (float*)d_out;

    int n = in_sizes[0];
    int vocab = in_sizes[3] / D;
    if (vocab > VOCAB_MAX) vocab = VOCAB_MAX;
    int nTiles = (n + TILE_M - 1) / TILE_M;

    int cblocks = (vocab * 2 + 255) / 256;
    convert_tables_kernel<<<cblocks, 256>>>(T1, T2, vocab);

    int grid = 148 * 4;
    if (grid > nTiles) grid = nTiles;
    wordemb_w8_kernel<<<grid, THREADS>>>(t1, t2, numf, W1, b1, W2, b2, out, n, nTiles);
}

// round 15
// speedup vs baseline: 1.8062x; 1.1279x over previous
#include <cuda_runtime.h>
#include <cuda_fp16.h>
#include <cstdint>
#include <math.h>

#define D        10
#define NUMF     16
#define DIN      36
#define H        128
#define CS1      1
#define CS2      3
#define TILE_M   128
#define THREADS  128

#define E1_TOK   130
#define E2_TOK   134
#define TOT_ROWS 264                // unified gather rows (<130 -> e1, else e2)
#define RWORDS   20                 // words per A row (40 fp16); 20r mod 32 -> LDSM conflict-free
#define VOCAB_MAX 65536

// fp16 tables: row = 16 halves (10 used) = 32B
__device__ uint4 g_T1h[VOCAB_MAX * 2];
__device__ uint4 g_T2h[VOCAB_MAX * 2];

__device__ __forceinline__ uint32_t h2pair(float a, float b) {
    __half2 h = __floats2half2_rn(a, b);
    return *reinterpret_cast<uint32_t*>(&h);
}

__global__ void convert_tables_kernel(const float* __restrict__ T1,
                                      const float* __restrict__ T2, int vocab) {
    int idx = blockIdx.x * blockDim.x + threadIdx.x;
    int total = vocab * 2;
    for (int e = idx; e < total; e += gridDim.x * blockDim.x) {
        int r = e >> 1, hf = e & 1;
        const float* r1 = T1 + r * D;
        const float* r2 = T2 + r * D;
        uint4 v1, v2;
        if (hf == 0) {
            v1.x = h2pair(r1[0], r1[1]); v1.y = h2pair(r1[2], r1[3]);
            v1.z = h2pair(r1[4], r1[5]); v1.w = h2pair(r1[6], r1[7]);
            v2.x = h2pair(r2[0], r2[1]); v2.y = h2pair(r2[2], r2[3]);
            v2.z = h2pair(r2[4], r2[5]); v2.w = h2pair(r2[6], r2[7]);
        } else {
            v1.x = h2pair(r1[8], r1[9]); v1.y = 0u; v1.z = 0u; v1.w = 0u;
            v2.x = h2pair(r2[8], r2[9]); v2.y = 0u; v2.z = 0u; v2.w = 0u;
        }
        g_T1h[e] = v1;
        g_T2h[e] = v2;
    }
}

__device__ __forceinline__ void load_rowh(const uint4* __restrict__ tab, int tok,
                                          uint32_t o[5]) {
    if (tok >= 0) {
        uint4 a = __ldg(tab + tok * 2);
        uint32_t b = __ldg(reinterpret_cast<const uint32_t*>(tab + tok * 2 + 1));
        o[0] = a.x; o[1] = a.y; o[2] = a.z; o[3] = a.w; o[4] = b;
    } else {
        o[0] = 0u; o[1] = 0u; o[2] = 0u; o[3] = 0u; o[4] = 0u;
    }
}

__device__ __forceinline__ void mma16(float d[4],
                                      uint32_t a0, uint32_t a1, uint32_t a2, uint32_t a3,
                                      uint32_t b0, uint32_t b1) {
    asm volatile(
        "mma.sync.aligned.m16n8k16.row.col.f32.f16.f16.f32 "
        "{%0,%1,%2,%3}, {%4,%5,%6,%7}, {%8,%9}, {%0,%1,%2,%3};"
        : "+f"(d[0]), "+f"(d[1]), "+f"(d[2]), "+f"(d[3])
        : "r"(a0), "r"(a1), "r"(a2), "r"(a3), "r"(b0), "r"(b1));
}
__device__ __forceinline__ void mma8(float d[4], uint32_t a0, uint32_t a1, uint32_t b0) {
    asm volatile(
        "mma.sync.aligned.m16n8k8.row.col.f32.f16.f16.f32 "
        "{%0,%1,%2,%3}, {%4,%5}, {%6}, {%0,%1,%2,%3};"
        : "+f"(d[0]), "+f"(d[1]), "+f"(d[2]), "+f"(d[3])
        : "r"(a0), "r"(a1), "r"(b0));
}
__device__ __forceinline__ void ldsm_x4(uint32_t& a0, uint32_t& a1, uint32_t& a2,
                                        uint32_t& a3, uint32_t addr) {
    asm volatile("ldmatrix.sync.aligned.m8n8.x4.shared.b16 {%0,%1,%2,%3}, [%4];"
                 : "=r"(a0), "=r"(a1), "=r"(a2), "=r"(a3) : "r"(addr));
}
__device__ __forceinline__ void ldsm_x2(uint32_t& a0, uint32_t& a1, uint32_t addr) {
    asm volatile("ldmatrix.sync.aligned.m8n8.x2.shared.b16 {%0,%1}, [%2];"
                 : "=r"(a0), "=r"(a1) : "r"(addr));
}

__global__ __launch_bounds__(THREADS, 6)
void wordemb_ldsm_kernel(
    const int*   __restrict__ t1,
    const int*   __restrict__ t2,
    const float* __restrict__ numf,
    const float* __restrict__ W1,
    const float* __restrict__ b1,
    const float* __restrict__ W2,
    const float* __restrict__ b2,
    float* __restrict__ out,
    int n, int nTiles)
{
    __shared__ __align__(16) uint32_t s_A[TILE_M * RWORDS];  // row-major A, 80B rows
    __shared__ uint32_t s_e1[E1_TOK * 5];   // half2 words, stride 5 (conflict-free)
    __shared__ uint32_t s_e2[E2_TOK * 5];
    __shared__ int   s_tk[2][TOT_ROWS];
    __shared__ float s_part[4][TILE_M];

    const int tid  = threadIdx.x;
    const int wid  = tid >> 5;
    const int lane = tid & 31;
    const float4* numf4 = reinterpret_cast<const float4*>(numf);

    // ---- B fragments (fp16), built once (bias folded at k==36) ----
    uint32_t B[4][5];
    float w2r[4][2];
    {
        const int nsub = lane >> 2;
        const int ksub = (lane & 3) * 2;
        #pragma unroll
        for (int j = 0; j < 4; j++) {
            int nn = wid * 32 + j * 8 + nsub;
            #pragma unroll
            for (int p = 0; p < 5; p++) {
                int k0 = p * 8 + ksub;
                float wv0 = (k0     < DIN) ? W1[k0 * H + nn]     : ((k0     == DIN) ? b1[nn] : 0.0f);
                float wv1 = (k0 + 1 < DIN) ? W1[(k0 + 1)*H + nn] : ((k0 + 1 == DIN) ? b1[nn] : 0.0f);
                B[j][p] = h2pair(wv0, wv1);
            }
            int nc = wid * 32 + j * 8 + (lane & 3) * 2;
            w2r[j][0] = W2[nc];
            w2r[j][1] = W2[nc + 1];
        }
    }
    const float b2v = b2[0];
    const int ar = lane >> 2;

    const __half2* e1h = reinterpret_cast<const __half2*>(s_e1);
    const __half2* e2h = reinterpret_cast<const __half2*>(s_e2);
    const uint32_t sA = (uint32_t)__cvta_generic_to_shared(s_A);
    // ldmatrix lane addressing: row_l = (l&7) + 8*((l>>3)&1); chunk offset 16*(l>>4)
    const int row_l = (lane & 7) + ((lane >> 3) & 1) * 8;
    const uint32_t loff4 = (uint32_t)(row_l * (RWORDS * 4)) + ((lane >> 4) << 4);
    const uint32_t loff2 = (uint32_t)(row_l * (RWORDS * 4));

    // ===== Prologue: tokens(t0); gather(t0); tokens(t1); numeric(t0) =====
    const int tile0 = blockIdx.x;
    {
        int r0g = tile0 * TILE_M;
        for (int er = tid; er < TOT_ROWS; er += THREADS) {
            int g = (er < E1_TOK) ? (r0g - CS1 + er) : (r0g - CS2 + (er - E1_TOK));
            int tok = -1;
            if (g >= 0 && g < n) tok = (er < E1_TOK) ? t1[g] : t2[g];
            s_tk[0][er] = tok;
        }
    }
    __syncthreads();
    for (int er = tid; er < TOT_ROWS; er += THREADS) {
        uint32_t o[5];
        const uint4* tab = (er < E1_TOK) ? g_T1h : g_T2h;
        load_rowh(tab, s_tk[0][er], o);
        uint32_t* dst = (er < E1_TOK) ? &s_e1[er * 5] : &s_e2[(er - E1_TOK) * 5];
        #pragma unroll
        for (int q = 0; q < 5; q++) dst[q] = o[q];
    }
    {
        int nt = tile0 + gridDim.x;
        if (nt < nTiles) {
            int r0g = nt * TILE_M;
            for (int er = tid; er < TOT_ROWS; er += THREADS) {
                int g = (er < E1_TOK) ? (r0g - CS1 + er) : (r0g - CS2 + (er - E1_TOK));
                int tok = -1;
                if (g >= 0 && g < n) tok = (er < E1_TOK) ? t1[g] : t2[g];
                s_tk[1][er] = tok;
            }
        }
    }
    // numeric(t0) for OWN row -> regs (nvh)
    uint32_t nvh[8];
    {
        int i0 = tile0 * TILE_M + tid;
        if (i0 < n) {
            #pragma unroll
            for (int c = 0; c < 4; c++) {
                float4 v = __ldg(numf4 + (size_t)i0 * 4 + c);
                nvh[2*c]     = h2pair(v.x, v.y);
                nvh[2*c + 1] = h2pair(v.z, v.w);
            }
        } else {
            #pragma unroll
            for (int q = 0; q < 8; q++) nvh[q] = 0u;
        }
    }
    __syncthreads();

    int p = 0;   // s_tk[p^1] holds tokens(t+1)
    for (int tile = tile0; tile < nTiles; tile += gridDim.x) {
        const int i = tile * TILE_M + tid;

        // ===== Phase A: x-build (half2 sums + numeric regs) -> row tid via 5x STS.128 =====
        {
            int lo1 = max(i - CS1, 0), hi1 = min(i + CS1 + 1, n);
            int lo2 = max(i - CS2, 0), hi2 = min(i + CS2 + 1, n);
            __half2 inv1 = __float2half2_rn(__fdividef(1.0f, (float)max(hi1 - lo1, 1)));
            __half2 inv2 = __float2half2_rn(__fdividef(1.0f, (float)max(hi2 - lo2, 1)));

            uint32_t w[10];
            #pragma unroll
            for (int q = 0; q < 5; q++) {
                __half2 a = e1h[(tid + 0) * 5 + q];
                __half2 b = e1h[(tid + 1) * 5 + q];
                __half2 c = e1h[(tid + 2) * 5 + q];
                __half2 r = __hmul2(__hadd2(__hadd2(a, b), c), inv1);
                w[q] = *reinterpret_cast<uint32_t*>(&r);
            }
            #pragma unroll
            for (int q = 0; q < 5; q++) {
                __half2 v0 = e2h[(tid + 0) * 5 + q];
                __half2 v1 = e2h[(tid + 1) * 5 + q];
                __half2 v2 = e2h[(tid + 2) * 5 + q];
                __half2 v3 = e2h[(tid + 3) * 5 + q];
                __half2 v4 = e2h[(tid + 4) * 5 + q];
                __half2 v5 = e2h[(tid + 5) * 5 + q];
                __half2 v6 = e2h[(tid + 6) * 5 + q];
                __half2 s = __hadd2(__hadd2(__hadd2(v0, v1), __hadd2(v2, v3)),
                                    __hadd2(__hadd2(v4, v5), v6));
                __half2 r = __hmul2(s, inv2);
                w[5 + q] = *reinterpret_cast<uint32_t*>(&r);
            }
            uint4* rowp = reinterpret_cast<uint4*>(&s_A[tid * RWORDS]);
            rowp[0] = make_uint4(w[0], w[1], w[2], w[3]);
            rowp[1] = make_uint4(w[4], w[5], w[6], w[7]);
            rowp[2] = make_uint4(w[8], w[9], nvh[0], nvh[1]);
            rowp[3] = make_uint4(nvh[2], nvh[3], nvh[4], nvh[5]);
            rowp[4] = make_uint4(nvh[6], nvh[7], 0x00003C00u, 0u);  // bias k=36
        }
        __syncthreads();

        // ===== Phase B: prefetch(t+1) + MMA =====
        const int nt1 = tile + gridDim.x;
        const int nt2 = nt1 + gridDim.x;
        const bool hasN1 = nt1 < nTiles;
        const bool hasN2 = nt2 < nTiles;

        uint32_t pg[3][5];
        if (hasN1) {
            #pragma unroll
            for (int u = 0; u < 3; u++) {
                int er = u * THREADS + tid;
                if (er < TOT_ROWS) {
                    const uint4* tab = (er < E1_TOK) ? g_T1h : g_T2h;
                    load_rowh(tab, s_tk[p ^ 1][er], pg[u]);
                }
            }
            int i1 = nt1 * TILE_M + tid;
            if (i1 < n) {
                #pragma unroll
                for (int c = 0; c < 4; c++) {
                    float4 v = __ldg(numf4 + (size_t)i1 * 4 + c);
                    nvh[2*c]     = h2pair(v.x, v.y);
                    nvh[2*c + 1] = h2pair(v.z, v.w);
                }
            } else {
                #pragma unroll
                for (int q = 0; q < 8; q++) nvh[q] = 0u;
            }
        }
        int ptk[3];
        if (hasN2) {
            int nr0 = nt2 * TILE_M;
            #pragma unroll
            for (int u = 0; u < 3; u++) {
                int er = u * THREADS + tid;
                int tok = -1;
                if (er < TOT_ROWS) {
                    int g = (er < E1_TOK) ? (nr0 - CS1 + er) : (nr0 - CS2 + (er - E1_TOK));
                    if (g >= 0 && g < n) tok = (er < E1_TOK) ? t1[g] : t2[g];
                }
                ptk[u] = tok;
            }
        }

        // ---- MMA over 8 m-tiles via ldmatrix ----
        #pragma unroll
        for (int mt = 0; mt < 8; mt++) {
            float Dacc[4][4];
            #pragma unroll
            for (int j = 0; j < 4; j++) {
                Dacc[j][0] = 0.f; Dacc[j][1] = 0.f; Dacc[j][2] = 0.f; Dacc[j][3] = 0.f;
            }
            const uint32_t mb = sA + (uint32_t)(mt * 16 * RWORDS * 4);

            uint32_t a0, a1, a2, a3;
            ldsm_x4(a0, a1, a2, a3, mb + loff4);           // k 0..15
            #pragma unroll
            for (int j = 0; j < 4; j++)
                mma16(Dacc[j], a0, a1, a2, a3, B[j][0], B[j][1]);
            ldsm_x4(a0, a1, a2, a3, mb + loff4 + 32);      // k 16..31
            #pragma unroll
            for (int j = 0; j < 4; j++)
                mma16(Dacc[j], a0, a1, a2, a3, B[j][2], B[j][3]);
            ldsm_x2(a0, a1, mb + loff2 + 64);              // k 32..39 (bias at 36)
            #pragma unroll
            for (int j = 0; j < 4; j++) mma8(Dacc[j], a0, a1, B[j][4]);

            float p0 = 0.0f, p1 = 0.0f;
            #pragma unroll
            for (int j = 0; j < 4; j++) {
                p0 = fmaf(fmaxf(Dacc[j][0], 0.f), w2r[j][0], p0);
                p0 = fmaf(fmaxf(Dacc[j][1], 0.f), w2r[j][1], p0);
                p1 = fmaf(fmaxf(Dacc[j][2], 0.f), w2r[j][0], p1);
                p1 = fmaf(fmaxf(Dacc[j][3], 0.f), w2r[j][1], p1);
            }
            p0 += __shfl_xor_sync(0xFFFFFFFF, p0, 1);
            p0 += __shfl_xor_sync(0xFFFFFFFF, p0, 2);
            p1 += __shfl_xor_sync(0xFFFFFFFF, p1, 1);
            p1 += __shfl_xor_sync(0xFFFFFFFF, p1, 2);
            if ((lane & 3) == 0) {
                s_part[wid][mt * 16 + ar]     = p0;
                s_part[wid][mt * 16 + ar + 8] = p1;
            }
        }

        // ---- write prefetched e-rows (s_e not read during MMA) ----
        if (hasN1) {
            #pragma unroll
            for (int u = 0; u < 3; u++) {
                int er = u * THREADS + tid;
                if (er < TOT_ROWS) {
                    uint32_t* dst = (er < E1_TOK) ? &s_e1[er * 5] : &s_e2[(er - E1_TOK) * 5];
                    #pragma unroll
                    for (int q = 0; q < 5; q++) dst[q] = pg[u][q];
                }
            }
        }
        __syncthreads();

        // ===== Phase C: out + token stash(t+2) =====
        if (i < n) {
            float s = s_part[0][tid] + s_part[1][tid] + s_part[2][tid] + s_part[3][tid] + b2v;
            out[i] = __fdividef(1.0f, 1.0f + __expf(-s));
        }
        if (hasN2) {
            #pragma unroll
            for (int u = 0; u < 3; u++) {
                int er = u * THREADS + tid;
                if (er < TOT_ROWS) s_tk[p][er] = ptk[u];
            }
        }
        __syncthreads();
        p ^= 1;
    }
}

extern "C" void kernel_launch(void* const* d_in, const int* in_sizes, int n_in,
                              void* d_out, int out_size) {
    const int*   t1   = (const int*)d_in[0];
    const int*   t2   = (const int*)d_in[1];
    const float* numf = (const float*)d_in[2];
    const float* T1   = (const float*)d_in[3];
    const float* T2   = (const float*)d_in[4];
    const float* W1   = (const float*)d_in[5];
    const float* b1   = (const float*)d_in[6];
    const float* W2   = (const float*)d_in[7];
    const float* b2   = (const float*)d_in[8];
    float* out = (float*)d_out;

    int n = in_sizes[0];
    int vocab = in_sizes[3] / D;
    if (vocab > VOCAB_MAX) vocab = VOCAB_MAX;
    int nTiles = (n + TILE_M - 1) / TILE_M;

    int cblocks = (vocab * 2 + 255) / 256;
    convert_tables_kernel<<<cblocks, 256>>>(T1, T2, vocab);

    int grid = 148 * 6;
    if (grid > nTiles) grid = nTiles;
    wordemb_ldsm_kernel<<<grid, THREADS>>>(t1, t2, numf, W1, b1, W2, b2, out, n, nTiles);
}

// round 16
// speedup vs baseline: 1.9840x; 1.0985x over previous
#include <cuda_runtime.h>
#include <cuda_fp16.h>
#include <cstdint>
#include <math.h>

#define D        10
#define NUMF     16
#define DIN      36
#define H        128
#define CS1      1
#define CS2      3
#define TILE_M   128
#define THREADS  128

#define E1_TOK   130
#define E2_TOK   134
#define TOT_ROWS 264                // unified gather rows (<130 -> e1, else e2)
#define RWORDS   20                 // words per A row; 20r mod 32 -> LDSM conflict-free
#define VOCAB_MAX 65536

// fp16 tables: row = 16 halves (10 used) = 32B
__device__ uint4 g_T1h[VOCAB_MAX * 2];
__device__ uint4 g_T2h[VOCAB_MAX * 2];

__device__ __forceinline__ uint32_t h2pair(float a, float b) {
    __half2 h = __floats2half2_rn(a, b);
    return *reinterpret_cast<uint32_t*>(&h);
}
__device__ __forceinline__ uint32_t hadd2u(uint32_t a, uint32_t b) {
    __half2 r = __hadd2(*reinterpret_cast<__half2*>(&a), *reinterpret_cast<__half2*>(&b));
    return *reinterpret_cast<uint32_t*>(&r);
}
__device__ __forceinline__ uint32_t hmul2u(uint32_t a, uint32_t b) {
    __half2 r = __hmul2(*reinterpret_cast<__half2*>(&a), *reinterpret_cast<__half2*>(&b));
    return *reinterpret_cast<uint32_t*>(&r);
}

__global__ void convert_tables_kernel(const float* __restrict__ T1,
                                      const float* __restrict__ T2, int vocab) {
    int idx = blockIdx.x * blockDim.x + threadIdx.x;
    int total = vocab * 2;
    for (int e = idx; e < total; e += gridDim.x * blockDim.x) {
        int r = e >> 1, hf = e & 1;
        const float* r1 = T1 + r * D;
        const float* r2 = T2 + r * D;
        uint4 v1, v2;
        if (hf == 0) {
            v1.x = h2pair(r1[0], r1[1]); v1.y = h2pair(r1[2], r1[3]);
            v1.z = h2pair(r1[4], r1[5]); v1.w = h2pair(r1[6], r1[7]);
            v2.x = h2pair(r2[0], r2[1]); v2.y = h2pair(r2[2], r2[3]);
            v2.z = h2pair(r2[4], r2[5]); v2.w = h2pair(r2[6], r2[7]);
        } else {
            v1.x = h2pair(r1[8], r1[9]); v1.y = 0u; v1.z = 0u; v1.w = 0u;
            v2.x = h2pair(r2[8], r2[9]); v2.y = 0u; v2.z = 0u; v2.w = 0u;
        }
        g_T1h[e] = v1;
        g_T2h[e] = v2;
    }
}

__device__ __forceinline__ void mma16(float d[4],
                                      uint32_t a0, uint32_t a1, uint32_t a2, uint32_t a3,
                                      uint32_t b0, uint32_t b1) {
    asm volatile(
        "mma.sync.aligned.m16n8k16.row.col.f32.f16.f16.f32 "
        "{%0,%1,%2,%3}, {%4,%5,%6,%7}, {%8,%9}, {%0,%1,%2,%3};"
        : "+f"(d[0]), "+f"(d[1]), "+f"(d[2]), "+f"(d[3])
        : "r"(a0), "r"(a1), "r"(a2), "r"(a3), "r"(b0), "r"(b1));
}
__device__ __forceinline__ void mma8(float d[4], uint32_t a0, uint32_t a1, uint32_t b0) {
    asm volatile(
        "mma.sync.aligned.m16n8k8.row.col.f32.f16.f16.f32 "
        "{%0,%1,%2,%3}, {%4,%5}, {%6}, {%0,%1,%2,%3};"
        : "+f"(d[0]), "+f"(d[1]), "+f"(d[2]), "+f"(d[3])
        : "r"(a0), "r"(a1), "r"(b0));
}
__device__ __forceinline__ void ldsm_x4(uint32_t& a0, uint32_t& a1, uint32_t& a2,
                                        uint32_t& a3, uint32_t addr) {
    asm volatile("ldmatrix.sync.aligned.m8n8.x4.shared.b16 {%0,%1,%2,%3}, [%4];"
                 : "=r"(a0), "=r"(a1), "=r"(a2), "=r"(a3) : "r"(addr));
}
__device__ __forceinline__ void ldsm_x2(uint32_t& a0, uint32_t& a1, uint32_t addr) {
    asm volatile("ldmatrix.sync.aligned.m8n8.x2.shared.b16 {%0,%1}, [%2];"
                 : "=r"(a0), "=r"(a1) : "r"(addr));
}
__device__ __forceinline__ void cpa16(uint32_t dst, const void* src, uint32_t srcsz) {
    asm volatile("cp.async.ca.shared.global [%0], [%1], 16, %2;"
                 :: "r"(dst), "l"(src), "r"(srcsz) : "memory");
}
__device__ __forceinline__ void cpa4(uint32_t dst, const void* src, uint32_t srcsz) {
    asm volatile("cp.async.ca.shared.global [%0], [%1], 4, %2;"
                 :: "r"(dst), "l"(src), "r"(srcsz) : "memory");
}
#define CP_COMMIT() asm volatile("cp.async.commit_group;" ::: "memory")
#define CP_WAIT0()  asm volatile("cp.async.wait_group 0;" ::: "memory")

__global__ __launch_bounds__(THREADS, 6)
void wordemb_cpa_kernel(
    const int*   __restrict__ t1,
    const int*   __restrict__ t2,
    const float* __restrict__ numf,
    const float* __restrict__ W1,
    const float* __restrict__ b1,
    const float* __restrict__ W2,
    const float* __restrict__ b2,
    float* __restrict__ out,
    int n, int nTiles)
{
    __shared__ __align__(16) uint32_t s_A[TILE_M * RWORDS];  // row-major A, 80B rows
    __shared__ __align__(16) uint4    s_eA1[E1_TOK];  // words 0-3 of each row (LDS.128 cf)
    __shared__ __align__(16) uint4    s_eA2[E2_TOK];
    __shared__ uint32_t s_eB1[E1_TOK];                // word 4 (LDS.32 cf)
    __shared__ uint32_t s_eB2[E2_TOK];
    __shared__ int   s_tk[2][TOT_ROWS];
    __shared__ float s_part[4][TILE_M];

    const int tid  = threadIdx.x;
    const int wid  = tid >> 5;
    const int lane = tid & 31;
    const float4* numf4 = reinterpret_cast<const float4*>(numf);

    const uint32_t sA1a = (uint32_t)__cvta_generic_to_shared(s_eA1);
    const uint32_t sA2a = (uint32_t)__cvta_generic_to_shared(s_eA2);
    const uint32_t sB1a = (uint32_t)__cvta_generic_to_shared(s_eB1);
    const uint32_t sB2a = (uint32_t)__cvta_generic_to_shared(s_eB2);

    // ---- B fragments (fp16), built once (bias folded at k==36) ----
    uint32_t B[4][5];
    float w2r[4][2];
    {
        const int nsub = lane >> 2;
        const int ksub = (lane & 3) * 2;
        #pragma unroll
        for (int j = 0; j < 4; j++) {
            int nn = wid * 32 + j * 8 + nsub;
            #pragma unroll
            for (int p = 0; p < 5; p++) {
                int k0 = p * 8 + ksub;
                float wv0 = (k0     < DIN) ? W1[k0 * H + nn]     : ((k0     == DIN) ? b1[nn] : 0.0f);
                float wv1 = (k0 + 1 < DIN) ? W1[(k0 + 1)*H + nn] : ((k0 + 1 == DIN) ? b1[nn] : 0.0f);
                B[j][p] = h2pair(wv0, wv1);
            }
            int nc = wid * 32 + j * 8 + (lane & 3) * 2;
            w2r[j][0] = W2[nc];
            w2r[j][1] = W2[nc + 1];
        }
    }
    const float b2v = b2[0];
    const int ar = lane >> 2;

    const uint32_t sA = (uint32_t)__cvta_generic_to_shared(s_A);
    const int row_l = (lane & 7) + ((lane >> 3) & 1) * 8;
    const uint32_t loff4 = (uint32_t)(row_l * (RWORDS * 4)) + ((lane >> 4) << 4);
    const uint32_t loff2 = (uint32_t)(row_l * (RWORDS * 4));

    // gather helper (issues 2 cp.async for unified row er using token set s)
    auto issue_gather = [&](const int* tks, int er) {
        int tok = tks[er];
        uint32_t sz16 = (tok >= 0) ? 16u : 0u;
        uint32_t sz4  = (tok >= 0) ? 4u  : 0u;
        int tk = (tok >= 0) ? tok : 0;
        if (er < E1_TOK) {
            const uint4* src = g_T1h + tk * 2;
            cpa16(sA1a + er * 16, src, sz16);
            cpa4 (sB1a + er * 4, reinterpret_cast<const uint32_t*>(src + 1), sz4);
        } else {
            int r2 = er - E1_TOK;
            const uint4* src = g_T2h + tk * 2;
            cpa16(sA2a + r2 * 16, src, sz16);
            cpa4 (sB2a + r2 * 4, reinterpret_cast<const uint32_t*>(src + 1), sz4);
        }
    };

    // ===== Prologue =====
    const int tile0 = blockIdx.x;
    {
        int r0g = tile0 * TILE_M;
        for (int er = tid; er < TOT_ROWS; er += THREADS) {
            int g = (er < E1_TOK) ? (r0g - CS1 + er) : (r0g - CS2 + (er - E1_TOK));
            int tok = -1;
            if (g >= 0 && g < n) tok = (er < E1_TOK) ? t1[g] : t2[g];
            s_tk[0][er] = tok;
        }
    }
    __syncthreads();
    for (int er = tid; er < TOT_ROWS; er += THREADS) issue_gather(s_tk[0], er);
    CP_COMMIT();
    {
        int nt = tile0 + gridDim.x;
        if (nt < nTiles) {
            int r0g = nt * TILE_M;
            for (int er = tid; er < TOT_ROWS; er += THREADS) {
                int g = (er < E1_TOK) ? (r0g - CS1 + er) : (r0g - CS2 + (er - E1_TOK));
                int tok = -1;
                if (g >= 0 && g < n) tok = (er < E1_TOK) ? t1[g] : t2[g];
                s_tk[1][er] = tok;
            }
        }
    }
    uint32_t nvh[8];
    {
        int i0 = tile0 * TILE_M + tid;
        if (i0 < n) {
            #pragma unroll
            for (int c = 0; c < 4; c++) {
                float4 v = __ldg(numf4 + (size_t)i0 * 4 + c);
                nvh[2*c]     = h2pair(v.x, v.y);
                nvh[2*c + 1] = h2pair(v.z, v.w);
            }
        } else {
            #pragma unroll
            for (int q = 0; q < 8; q++) nvh[q] = 0u;
        }
    }
    CP_WAIT0();
    __syncthreads();

    int p = 0;   // s_tk[p^1] holds tokens(t+1)
    for (int tile = tile0; tile < nTiles; tile += gridDim.x) {
        const int i = tile * TILE_M + tid;

        // ===== Phase A: vectorized window sums -> A row (5x STS.128) =====
        {
            int lo1 = max(i - CS1, 0), hi1 = min(i + CS1 + 1, n);
            int lo2 = max(i - CS2, 0), hi2 = min(i + CS2 + 1, n);
            __half2 i1h = __float2half2_rn(__fdividef(1.0f, (float)max(hi1 - lo1, 1)));
            __half2 i2h = __float2half2_rn(__fdividef(1.0f, (float)max(hi2 - lo2, 1)));
            uint32_t inv1 = *reinterpret_cast<uint32_t*>(&i1h);
            uint32_t inv2 = *reinterpret_cast<uint32_t*>(&i2h);

            // e1: rows tid..tid+2
            uint4 a0 = s_eA1[tid], a1 = s_eA1[tid + 1], a2 = s_eA1[tid + 2];
            uint32_t b0 = s_eB1[tid], b1v = s_eB1[tid + 1], b2w = s_eB1[tid + 2];
            uint32_t w[10];
            w[0] = hmul2u(hadd2u(hadd2u(a0.x, a1.x), a2.x), inv1);
            w[1] = hmul2u(hadd2u(hadd2u(a0.y, a1.y), a2.y), inv1);
            w[2] = hmul2u(hadd2u(hadd2u(a0.z, a1.z), a2.z), inv1);
            w[3] = hmul2u(hadd2u(hadd2u(a0.w, a1.w), a2.w), inv1);
            w[4] = hmul2u(hadd2u(hadd2u(b0, b1v), b2w), inv1);

            // e2: rows tid..tid+6
            uint4 c = s_eA2[tid];
            uint32_t cb = s_eB2[tid];
            uint32_t s0 = c.x, s1 = c.y, s2 = c.z, s3 = c.w, s4 = cb;
            #pragma unroll
            for (int wdx = 1; wdx < 7; wdx++) {
                uint4 d_ = s_eA2[tid + wdx];
                uint32_t db = s_eB2[tid + wdx];
                s0 = hadd2u(s0, d_.x); s1 = hadd2u(s1, d_.y);
                s2 = hadd2u(s2, d_.z); s3 = hadd2u(s3, d_.w);
                s4 = hadd2u(s4, db);
            }
            w[5] = hmul2u(s0, inv2);
            w[6] = hmul2u(s1, inv2);
            w[7] = hmul2u(s2, inv2);
            w[8] = hmul2u(s3, inv2);
            w[9] = hmul2u(s4, inv2);

            uint4* rowp = reinterpret_cast<uint4*>(&s_A[tid * RWORDS]);
            rowp[0] = make_uint4(w[0], w[1], w[2], w[3]);
            rowp[1] = make_uint4(w[4], w[5], w[6], w[7]);
            rowp[2] = make_uint4(w[8], w[9], nvh[0], nvh[1]);
            rowp[3] = make_uint4(nvh[2], nvh[3], nvh[4], nvh[5]);
            rowp[4] = make_uint4(nvh[6], nvh[7], 0x00003C00u, 0u);  // bias k=36
        }
        __syncthreads();

        // ===== Phase B: cp.async gather(t+1) + prefetch + MMA =====
        const int nt1 = tile + gridDim.x;
        const int nt2 = nt1 + gridDim.x;
        const bool hasN1 = nt1 < nTiles;
        const bool hasN2 = nt2 < nTiles;

        if (hasN1) {
            for (int er = tid; er < TOT_ROWS; er += THREADS) issue_gather(s_tk[p ^ 1], er);
            int i1 = nt1 * TILE_M + tid;
            if (i1 < n) {
                #pragma unroll
                for (int c = 0; c < 4; c++) {
                    float4 v = __ldg(numf4 + (size_t)i1 * 4 + c);
                    nvh[2*c]     = h2pair(v.x, v.y);
                    nvh[2*c + 1] = h2pair(v.z, v.w);
                }
            } else {
                #pragma unroll
                for (int q = 0; q < 8; q++) nvh[q] = 0u;
            }
        }
        CP_COMMIT();
        int ptk[3];
        if (hasN2) {
            int nr0 = nt2 * TILE_M;
            #pragma unroll
            for (int u = 0; u < 3; u++) {
                int er = u * THREADS + tid;
                int tok = -1;
                if (er < TOT_ROWS) {
                    int g = (er < E1_TOK) ? (nr0 - CS1 + er) : (nr0 - CS2 + (er - E1_TOK));
                    if (g >= 0 && g < n) tok = (er < E1_TOK) ? t1[g] : t2[g];
                }
                ptk[u] = tok;
            }
        }

        // ---- MMA over 8 m-tiles via ldmatrix ----
        #pragma unroll
        for (int mt = 0; mt < 8; mt++) {
            float Dacc[4][4];
            #pragma unroll
            for (int j = 0; j < 4; j++) {
                Dacc[j][0] = 0.f; Dacc[j][1] = 0.f; Dacc[j][2] = 0.f; Dacc[j][3] = 0.f;
            }
            const uint32_t mb = sA + (uint32_t)(mt * 16 * RWORDS * 4);

            uint32_t a0, a1, a2, a3;
            ldsm_x4(a0, a1, a2, a3, mb + loff4);           // k 0..15
            #pragma unroll
            for (int j = 0; j < 4; j++)
                mma16(Dacc[j], a0, a1, a2, a3, B[j][0], B[j][1]);
            ldsm_x4(a0, a1, a2, a3, mb + loff4 + 32);      // k 16..31
            #pragma unroll
            for (int j = 0; j < 4; j++)
                mma16(Dacc[j], a0, a1, a2, a3, B[j][2], B[j][3]);
            ldsm_x2(a0, a1, mb + loff2 + 64);              // k 32..39 (bias at 36)
            #pragma unroll
            for (int j = 0; j < 4; j++) mma8(Dacc[j], a0, a1, B[j][4]);

            float p0 = 0.0f, p1 = 0.0f;
            #pragma unroll
            for (int j = 0; j < 4; j++) {
                p0 = fmaf(fmaxf(Dacc[j][0], 0.f), w2r[j][0], p0);
                p0 = fmaf(fmaxf(Dacc[j][1], 0.f), w2r[j][1], p0);
                p1 = fmaf(fmaxf(Dacc[j][2], 0.f), w2r[j][0], p1);
                p1 = fmaf(fmaxf(Dacc[j][3], 0.f), w2r[j][1], p1);
            }
            p0 += __shfl_xor_sync(0xFFFFFFFF, p0, 1);
            p0 += __shfl_xor_sync(0xFFFFFFFF, p0, 2);
            p1 += __shfl_xor_sync(0xFFFFFFFF, p1, 1);
            p1 += __shfl_xor_sync(0xFFFFFFFF, p1, 2);
            if ((lane & 3) == 0) {
                s_part[wid][mt * 16 + ar]     = p0;
                s_part[wid][mt * 16 + ar + 8] = p1;
            }
        }

        CP_WAIT0();        // gather(t+1) landed in s_e
        __syncthreads();

        // ===== Phase C: out + token stash(t+2) =====
        if (i < n) {
            float s = s_part[0][tid] + s_part[1][tid] + s_part[2][tid] + s_part[3][tid] + b2v;
            out[i] = __fdividef(1.0f, 1.0f + __expf(-s));
        }
        if (hasN2) {
            #pragma unroll
            for (int u = 0; u < 3; u++) {
                int er = u * THREADS + tid;
                if (er < TOT_ROWS) s_tk[p][er] = ptk[u];
            }
        }
        __syncthreads();
        p ^= 1;
    }
}

extern "C" void kernel_launch(void* const* d_in, const int* in_sizes, int n_in,
                              void* d_out, int out_size) {
    const int*   t1   = (const int*)d_in[0];
    const int*   t2   = (const int*)d_in[1];
    const float* numf = (const float*)d_in[2];
    const float* T1   = (const float*)d_in[3];
    const float* T2   = (const float*)d_in[4];
    const float* W1   = (const float*)d_in[5];
    const float* b1   = (const float*)d_in[6];
    const float* W2   = (const float*)d_in[7];
    const float* b2   = (const float*)d_in[8];
    float* out = (float*)d_out;

    int n = in_sizes[0];
    int vocab = in_sizes[3] / D;
    if (vocab > VOCAB_MAX) vocab = VOCAB_MAX;
    int nTiles = (n + TILE_M - 1) / TILE_M;

    int cblocks = (vocab * 2 + 255) / 256;
    convert_tables_kernel<<<cblocks, 256>>>(T1, T2, vocab);

    int grid = 148 * 6;
    if (grid > nTiles) grid = nTiles;
    wordemb_cpa_kernel<<<grid, THREADS>>>(t1, t2, numf, W1, b1, W2, b2, out, n, nTiles);
}

// round 17
// speedup vs baseline: 2.0619x; 1.0393x over previous
#include <cuda_runtime.h>
#include <cuda_fp16.h>
#include <cstdint>
#include <math.h>

#define D        10
#define NUMF     16
#define DIN      36
#define H        128
#define CS1      1
#define CS2      3
#define TILE_M   128
#define THREADS  128

#define E1_TOK   130
#define E2_TOK   134
#define TOT_ROWS 264                // unified gather rows (<130 -> e1, else e2)
#define RWORDS   20                 // words per A row; 20r mod 32 -> LDSM conflict-free
#define VOCAB_MAX 65536

// fp16 tables: row = 16 halves (10 used) = 32B
__device__ uint4 g_T1h[VOCAB_MAX * 2];
__device__ uint4 g_T2h[VOCAB_MAX * 2];

__device__ __forceinline__ uint32_t h2pair(float a, float b) {
    __half2 h = __floats2half2_rn(a, b);
    return *reinterpret_cast<uint32_t*>(&h);
}
__device__ __forceinline__ uint32_t hadd2u(uint32_t a, uint32_t b) {
    __half2 r = __hadd2(*reinterpret_cast<__half2*>(&a), *reinterpret_cast<__half2*>(&b));
    return *reinterpret_cast<uint32_t*>(&r);
}
__device__ __forceinline__ uint32_t hmul2u(uint32_t a, uint32_t b) {
    __half2 r = __hmul2(*reinterpret_cast<__half2*>(&a), *reinterpret_cast<__half2*>(&b));
    return *reinterpret_cast<uint32_t*>(&r);
}

__global__ void convert_tables_kernel(const float* __restrict__ T1,
                                      const float* __restrict__ T2, int vocab) {
    int idx = blockIdx.x * blockDim.x + threadIdx.x;
    int total = vocab * 2;
    for (int e = idx; e < total; e += gridDim.x * blockDim.x) {
        int r = e >> 1, hf = e & 1;
        const float* r1 = T1 + r * D;
        const float* r2 = T2 + r * D;
        uint4 v1, v2;
        if (hf == 0) {
            v1.x = h2pair(r1[0], r1[1]); v1.y = h2pair(r1[2], r1[3]);
            v1.z = h2pair(r1[4], r1[5]); v1.w = h2pair(r1[6], r1[7]);
            v2.x = h2pair(r2[0], r2[1]); v2.y = h2pair(r2[2], r2[3]);
            v2.z = h2pair(r2[4], r2[5]); v2.w = h2pair(r2[6], r2[7]);
        } else {
            v1.x = h2pair(r1[8], r1[9]); v1.y = 0u; v1.z = 0u; v1.w = 0u;
            v2.x = h2pair(r2[8], r2[9]); v2.y = 0u; v2.z = 0u; v2.w = 0u;
        }
        g_T1h[e] = v1;
        g_T2h[e] = v2;
    }
}

__device__ __forceinline__ void mma16(float d[4],
                                      uint32_t a0, uint32_t a1, uint32_t a2, uint32_t a3,
                                      uint32_t b0, uint32_t b1) {
    asm volatile(
        "mma.sync.aligned.m16n8k16.row.col.f32.f16.f16.f32 "
        "{%0,%1,%2,%3}, {%4,%5,%6,%7}, {%8,%9}, {%0,%1,%2,%3};"
        : "+f"(d[0]), "+f"(d[1]), "+f"(d[2]), "+f"(d[3])
        : "r"(a0), "r"(a1), "r"(a2), "r"(a3), "r"(b0), "r"(b1));
}
__device__ __forceinline__ void mma8(float d[4], uint32_t a0, uint32_t a1, uint32_t b0) {
    asm volatile(
        "mma.sync.aligned.m16n8k8.row.col.f32.f16.f16.f32 "
        "{%0,%1,%2,%3}, {%4,%5}, {%6}, {%0,%1,%2,%3};"
        : "+f"(d[0]), "+f"(d[1]), "+f"(d[2]), "+f"(d[3])
        : "r"(a0), "r"(a1), "r"(b0));
}
__device__ __forceinline__ void ldsm_x4(uint32_t& a0, uint32_t& a1, uint32_t& a2,
                                        uint32_t& a3, uint32_t addr) {
    asm volatile("ldmatrix.sync.aligned.m8n8.x4.shared.b16 {%0,%1,%2,%3}, [%4];"
                 : "=r"(a0), "=r"(a1), "=r"(a2), "=r"(a3) : "r"(addr));
}
__device__ __forceinline__ void ldsm_x2(uint32_t& a0, uint32_t& a1, uint32_t addr) {
    asm volatile("ldmatrix.sync.aligned.m8n8.x2.shared.b16 {%0,%1}, [%2];"
                 : "=r"(a0), "=r"(a1) : "r"(addr));
}
__device__ __forceinline__ void cpa16(uint32_t dst, const void* src, uint32_t srcsz) {
    asm volatile("cp.async.ca.shared.global [%0], [%1], 16, %2;"
                 :: "r"(dst), "l"(src), "r"(srcsz) : "memory");
}
__device__ __forceinline__ void cpa4(uint32_t dst, const void* src, uint32_t srcsz) {
    asm volatile("cp.async.ca.shared.global [%0], [%1], 4, %2;"
                 :: "r"(dst), "l"(src), "r"(srcsz) : "memory");
}
#define CP_COMMIT() asm volatile("cp.async.commit_group;" ::: "memory")
#define CP_WAIT0()  asm volatile("cp.async.wait_group 0;" ::: "memory")

__global__ __launch_bounds__(THREADS, 6)
void wordemb_nc_kernel(
    const int*   __restrict__ t1,
    const int*   __restrict__ t2,
    const float* __restrict__ numf,
    const float* __restrict__ W1,
    const float* __restrict__ b1,
    const float* __restrict__ W2,
    const float* __restrict__ b2,
    float* __restrict__ out,
    int n, int nTiles)
{
    __shared__ __align__(16) uint32_t s_A[TILE_M * RWORDS];  // row-major A, 80B rows
    __shared__ __align__(16) uint4    s_eA1[E1_TOK];
    __shared__ __align__(16) uint4    s_eA2[E2_TOK];
    __shared__ uint32_t s_eB1[E1_TOK];
    __shared__ uint32_t s_eB2[E2_TOK];
    __shared__ int   s_tk[2][TOT_ROWS];
    __shared__ float s_part[4][TILE_M];

    const int tid  = threadIdx.x;
    const int wid  = tid >> 5;
    const int lane = tid & 31;
    const float4* numf4 = reinterpret_cast<const float4*>(numf);
    const long nF4 = (long)n * 4;

    const uint32_t sA1a = (uint32_t)__cvta_generic_to_shared(s_eA1);
    const uint32_t sA2a = (uint32_t)__cvta_generic_to_shared(s_eA2);
    const uint32_t sB1a = (uint32_t)__cvta_generic_to_shared(s_eB1);
    const uint32_t sB2a = (uint32_t)__cvta_generic_to_shared(s_eB2);

    // ---- B fragments (fp16), built once (bias folded at k==36) ----
    uint32_t B[4][5];
    float w2r[4][2];
    {
        const int nsub = lane >> 2;
        const int ksub = (lane & 3) * 2;
        #pragma unroll
        for (int j = 0; j < 4; j++) {
            int nn = wid * 32 + j * 8 + nsub;
            #pragma unroll
            for (int p = 0; p < 5; p++) {
                int k0 = p * 8 + ksub;
                float wv0 = (k0     < DIN) ? W1[k0 * H + nn]     : ((k0     == DIN) ? b1[nn] : 0.0f);
                float wv1 = (k0 + 1 < DIN) ? W1[(k0 + 1)*H + nn] : ((k0 + 1 == DIN) ? b1[nn] : 0.0f);
                B[j][p] = h2pair(wv0, wv1);
            }
            int nc = wid * 32 + j * 8 + (lane & 3) * 2;
            w2r[j][0] = W2[nc];
            w2r[j][1] = W2[nc + 1];
        }
    }
    const float b2v = b2[0];
    const int ar = lane >> 2;

    const uint32_t sA = (uint32_t)__cvta_generic_to_shared(s_A);
    const int row_l = (lane & 7) + ((lane >> 3) & 1) * 8;
    const uint32_t loff4 = (uint32_t)(row_l * (RWORDS * 4)) + ((lane >> 4) << 4);
    const uint32_t loff2 = (uint32_t)(row_l * (RWORDS * 4));

    auto issue_gather = [&](const int* tks, int er) {
        int tok = tks[er];
        uint32_t sz16 = (tok >= 0) ? 16u : 0u;
        uint32_t sz4  = (tok >= 0) ? 4u  : 0u;
        int tk = (tok >= 0) ? tok : 0;
        if (er < E1_TOK) {
            const uint4* src = g_T1h + tk * 2;
            cpa16(sA1a + er * 16, src, sz16);
            cpa4 (sB1a + er * 4, reinterpret_cast<const uint32_t*>(src + 1), sz4);
        } else {
            int r2 = er - E1_TOK;
            const uint4* src = g_T2h + tk * 2;
            cpa16(sA2a + r2 * 16, src, sz16);
            cpa4 (sB2a + r2 * 4, reinterpret_cast<const uint32_t*>(src + 1), sz4);
        }
    };

    // coalesced numeric: thread handles element e = u*128+tid -> row e>>2, quarter e&3
    const int nrow0 = tid >> 2;          // row for u=0 (rows 0..31)
    const int nq    = tid & 3;

    // ===== Prologue =====
    const int tile0 = blockIdx.x;
    {
        int r0g = tile0 * TILE_M;
        for (int er = tid; er < TOT_ROWS; er += THREADS) {
            int g = (er < E1_TOK) ? (r0g - CS1 + er) : (r0g - CS2 + (er - E1_TOK));
            int tok = -1;
            if (g >= 0 && g < n) tok = (er < E1_TOK) ? t1[g] : t2[g];
            s_tk[0][er] = tok;
        }
    }
    __syncthreads();
    for (int er = tid; er < TOT_ROWS; er += THREADS) issue_gather(s_tk[0], er);
    CP_COMMIT();
    {
        int nt = tile0 + gridDim.x;
        if (nt < nTiles) {
            int r0g = nt * TILE_M;
            for (int er = tid; er < TOT_ROWS; er += THREADS) {
                int g = (er < E1_TOK) ? (r0g - CS1 + er) : (r0g - CS2 + (er - E1_TOK));
                int tok = -1;
                if (g >= 0 && g < n) tok = (er < E1_TOK) ? t1[g] : t2[g];
                s_tk[1][er] = tok;
            }
        }
    }
    // numeric(t0): coalesced load + scatter into A rows (words 10..17)
    {
        #pragma unroll
        for (int u = 0; u < 4; u++) {
            int e = u * THREADS + tid;
            long gf4 = (long)tile0 * (TILE_M * 4) + e;
            float4 v = (gf4 < nF4) ? __ldg(numf4 + gf4) : make_float4(0.f, 0.f, 0.f, 0.f);
            int row = nrow0 + u * 32;
            uint2 pw = make_uint2(h2pair(v.x, v.y), h2pair(v.z, v.w));
            *reinterpret_cast<uint2*>(&s_A[row * RWORDS + 10 + 2 * nq]) = pw;
        }
    }
    // bias words (constant for all tiles)
    s_A[tid * RWORDS + 18] = 0x00003C00u;
    s_A[tid * RWORDS + 19] = 0u;
    CP_WAIT0();
    __syncthreads();

    int p = 0;   // s_tk[p^1] holds tokens(t+1)
    for (int tile = tile0; tile < nTiles; tile += gridDim.x) {
        const int i = tile * TILE_M + tid;

        // ===== Phase A: window sums -> A row words 0..9 =====
        {
            int lo1 = max(i - CS1, 0), hi1 = min(i + CS1 + 1, n);
            int lo2 = max(i - CS2, 0), hi2 = min(i + CS2 + 1, n);
            __half2 i1h = __float2half2_rn(__fdividef(1.0f, (float)max(hi1 - lo1, 1)));
            __half2 i2h = __float2half2_rn(__fdividef(1.0f, (float)max(hi2 - lo2, 1)));
            uint32_t inv1 = *reinterpret_cast<uint32_t*>(&i1h);
            uint32_t inv2 = *reinterpret_cast<uint32_t*>(&i2h);

            uint4 a0 = s_eA1[tid], a1 = s_eA1[tid + 1], a2 = s_eA1[tid + 2];
            uint32_t b0 = s_eB1[tid], b1v = s_eB1[tid + 1], b2w = s_eB1[tid + 2];
            uint32_t w[10];
            w[0] = hmul2u(hadd2u(hadd2u(a0.x, a1.x), a2.x), inv1);
            w[1] = hmul2u(hadd2u(hadd2u(a0.y, a1.y), a2.y), inv1);
            w[2] = hmul2u(hadd2u(hadd2u(a0.z, a1.z), a2.z), inv1);
            w[3] = hmul2u(hadd2u(hadd2u(a0.w, a1.w), a2.w), inv1);
            w[4] = hmul2u(hadd2u(hadd2u(b0, b1v), b2w), inv1);

            uint4 c = s_eA2[tid];
            uint32_t cb = s_eB2[tid];
            uint32_t s0 = c.x, s1 = c.y, s2 = c.z, s3 = c.w, s4 = cb;
            #pragma unroll
            for (int wdx = 1; wdx < 7; wdx++) {
                uint4 d_ = s_eA2[tid + wdx];
                uint32_t db = s_eB2[tid + wdx];
                s0 = hadd2u(s0, d_.x); s1 = hadd2u(s1, d_.y);
                s2 = hadd2u(s2, d_.z); s3 = hadd2u(s3, d_.w);
                s4 = hadd2u(s4, db);
            }
            w[5] = hmul2u(s0, inv2);
            w[6] = hmul2u(s1, inv2);
            w[7] = hmul2u(s2, inv2);
            w[8] = hmul2u(s3, inv2);
            w[9] = hmul2u(s4, inv2);

            uint4* rowp = reinterpret_cast<uint4*>(&s_A[tid * RWORDS]);
            rowp[0] = make_uint4(w[0], w[1], w[2], w[3]);
            rowp[1] = make_uint4(w[4], w[5], w[6], w[7]);
            *reinterpret_cast<uint2*>(&s_A[tid * RWORDS + 8]) = make_uint2(w[8], w[9]);
        }
        __syncthreads();

        // ===== Phase B: cp.async gather(t+1) + coalesced numeric(t+1) + MMA =====
        const int nt1 = tile + gridDim.x;
        const int nt2 = nt1 + gridDim.x;
        const bool hasN1 = nt1 < nTiles;
        const bool hasN2 = nt2 < nTiles;

        uint32_t nvh[8];
        if (hasN1) {
            for (int er = tid; er < TOT_ROWS; er += THREADS) issue_gather(s_tk[p ^ 1], er);
            #pragma unroll
            for (int u = 0; u < 4; u++) {
                int e = u * THREADS + tid;
                long gf4 = (long)nt1 * (TILE_M * 4) + e;
                float4 v = (gf4 < nF4) ? __ldg(numf4 + gf4) : make_float4(0.f, 0.f, 0.f, 0.f);
                nvh[2*u]     = h2pair(v.x, v.y);
                nvh[2*u + 1] = h2pair(v.z, v.w);
            }
        }
        CP_COMMIT();
        int ptk[3];
        if (hasN2) {
            int nr0 = nt2 * TILE_M;
            #pragma unroll
            for (int u = 0; u < 3; u++) {
                int er = u * THREADS + tid;
                int tok = -1;
                if (er < TOT_ROWS) {
                    int g = (er < E1_TOK) ? (nr0 - CS1 + er) : (nr0 - CS2 + (er - E1_TOK));
                    if (g >= 0 && g < n) tok = (er < E1_TOK) ? t1[g] : t2[g];
                }
                ptk[u] = tok;
            }
        }

        // ---- MMA over 8 m-tiles via ldmatrix ----
        #pragma unroll
        for (int mt = 0; mt < 8; mt++) {
            float Dacc[4][4];
            #pragma unroll
            for (int j = 0; j < 4; j++) {
                Dacc[j][0] = 0.f; Dacc[j][1] = 0.f; Dacc[j][2] = 0.f; Dacc[j][3] = 0.f;
            }
            const uint32_t mb = sA + (uint32_t)(mt * 16 * RWORDS * 4);

            uint32_t a0, a1, a2, a3;
            ldsm_x4(a0, a1, a2, a3, mb + loff4);
            #pragma unroll
            for (int j = 0; j < 4; j++)
                mma16(Dacc[j], a0, a1, a2, a3, B[j][0], B[j][1]);
            ldsm_x4(a0, a1, a2, a3, mb + loff4 + 32);
            #pragma unroll
            for (int j = 0; j < 4; j++)
                mma16(Dacc[j], a0, a1, a2, a3, B[j][2], B[j][3]);
            ldsm_x2(a0, a1, mb + loff2 + 64);
            #pragma unroll
            for (int j = 0; j < 4; j++) mma8(Dacc[j], a0, a1, B[j][4]);

            float p0 = 0.0f, p1 = 0.0f;
            #pragma unroll
            for (int j = 0; j < 4; j++) {
                p0 = fmaf(fmaxf(Dacc[j][0], 0.f), w2r[j][0], p0);
                p0 = fmaf(fmaxf(Dacc[j][1], 0.f), w2r[j][1], p0);
                p1 = fmaf(fmaxf(Dacc[j][2], 0.f), w2r[j][0], p1);
                p1 = fmaf(fmaxf(Dacc[j][3], 0.f), w2r[j][1], p1);
            }
            p0 += __shfl_xor_sync(0xFFFFFFFF, p0, 1);
            p0 += __shfl_xor_sync(0xFFFFFFFF, p0, 2);
            p1 += __shfl_xor_sync(0xFFFFFFFF, p1, 1);
            p1 += __shfl_xor_sync(0xFFFFFFFF, p1, 2);
            if ((lane & 3) == 0) {
                s_part[wid][mt * 16 + ar]     = p0;
                s_part[wid][mt * 16 + ar + 8] = p1;
            }
        }

        CP_WAIT0();        // gather(t+1) landed
        __syncthreads();   // MMA reads done; s_part visible

        // ===== Phase C: out + numeric(t+1) scatter + token stash(t+2) =====
        if (i < n) {
            float s = s_part[0][tid] + s_part[1][tid] + s_part[2][tid] + s_part[3][tid] + b2v;
            out[i] = __fdividef(1.0f, 1.0f + __expf(-s));
        }
        if (hasN1) {
            #pragma unroll
            for (int u = 0; u < 4; u++) {
                int row = nrow0 + u * 32;
                *reinterpret_cast<uint2*>(&s_A[row * RWORDS + 10 + 2 * nq]) =
                    make_uint2(nvh[2*u], nvh[2*u + 1]);
            }
        }
        if (hasN2) {
            #pragma unroll
            for (int u = 0; u < 3; u++) {
                int er = u * THREADS + tid;
                if (er < TOT_ROWS) s_tk[p][er] = ptk[u];
            }
        }
        __syncthreads();
        p ^= 1;
    }
}

extern "C" void kernel_launch(void* const* d_in, const int* in_sizes, int n_in,
                              void* d_out, int out_size) {
    const int*   t1   = (const int*)d_in[0];
    const int*   t2   = (const int*)d_in[1];
    const float* numf = (const float*)d_in[2];
    const float* T1   = (const float*)d_in[3];
    const float* T2   = (const float*)d_in[4];
    const float* W1   = (const float*)d_in[5];
    const float* b1   = (const float*)d_in[6];
    const float* W2   = (const float*)d_in[7];
    const float* b2   = (const float*)d_in[8];
    float* out = (float*)d_out;

    int n = in_sizes[0];
    int vocab = in_sizes[3] / D;
    if (vocab > VOCAB_MAX) vocab = VOCAB_MAX;
    int nTiles = (n + TILE_M - 1) / TILE_M;

    int cblocks = (vocab * 2 + 255) / 256;
    convert_tables_kernel<<<cblocks, 256>>>(T1, T2, vocab);

    int grid = 148 * 6;
    if (grid > nTiles) grid = nTiles;
    wordemb_nc_kernel<<<grid, THREADS>>>(t1, t2, numf, W1, b1, W2, b2, out, n, nTiles);
}